// round 17
// baseline (speedup 1.0000x reference)
#include <cuda_runtime.h>
#include <cuda_fp16.h>
#include <math.h>
#include <stdint.h>

#define Bsz 4
#define SEQ 2048
#define DIM 512
#define NH  8
#define HDm 64
#define FFm 1024
#define C2m 128
#define HFm 64
#define WFm 64
#define EPSf 1e-6f

// ---------------- static scratch ----------------
__device__ float g_x   [Bsz*SEQ*DIM];
__device__ float g_x2  [Bsz*SEQ*DIM];
__device__ __half g_feats_h[Bsz*SEQ*C2m];
__device__ __half g_xn_h  [Bsz*SEQ*DIM];
__device__ __half g_qkv_h [Bsz*SEQ*3*DIM];
__device__ __half g_o_h   [Bsz*SEQ*DIM];
__device__ __half g_xn2_h [Bsz*SEQ*DIM];
__device__ __half g_hh    [Bsz*SEQ*2*FFm];
__device__ __half g_hg_h  [Bsz*SEQ*FFm];
__device__ __half g_wcorr_h[DIM*C2m];
__device__ __half g_wqkv_h [3*DIM*DIM];
__device__ __half g_wout_h [DIM*DIM];
__device__ __half g_wff1_h [2*FFm*DIM];
__device__ __half g_wff2_h [DIM*FFm];

__device__ __forceinline__ float warpSum(float v){
    #pragma unroll
    for (int o = 16; o > 0; o >>= 1) v += __shfl_xor_sync(0xFFFFFFFFu, v, o);
    return v;
}
__device__ __forceinline__ uint32_t pkh2(float x, float y){
    __half2 h = __floats2half2_rn(x, y);
    return *reinterpret_cast<uint32_t*>(&h);
}
__device__ __forceinline__ float geluf(float g){
    return 0.5f * g * (1.f + erff(g * 0.70710678118654752f));
}
__device__ __forceinline__ void mma_f16(float* c, const uint32_t* a, uint32_t b0, uint32_t b1){
    asm volatile(
        "mma.sync.aligned.m16n8k16.row.col.f32.f16.f16.f32 "
        "{%0,%1,%2,%3}, {%4,%5,%6,%7}, {%8,%9}, {%0,%1,%2,%3};"
        : "+f"(c[0]), "+f"(c[1]), "+f"(c[2]), "+f"(c[3])
        : "r"(a[0]), "r"(a[1]), "r"(a[2]), "r"(a[3]), "r"(b0), "r"(b1));
}
__device__ __forceinline__ void cp16(uint32_t smaddr, const void* g){
    asm volatile("cp.async.cg.shared.global [%0], [%1], 16;" :: "r"(smaddr), "l"(g));
}
#define CP_COMMIT() asm volatile("cp.async.commit_group;" ::: "memory")
#define CP_WAIT2()  asm volatile("cp.async.wait_group 2;" ::: "memory")
#define CP_WAIT0()  asm volatile("cp.async.wait_group 0;" ::: "memory")

// ---------------- fused weight conversion ----------------
#define WC_N0 ((DIM*C2m)/4)
#define WC_N1 ((3*DIM*DIM)/4)
#define WC_N2 ((DIM*DIM)/4)
#define WC_N3 ((2*FFm*DIM)/4)
#define WC_N4 ((DIM*FFm)/4)
#define WC_TOT (WC_N0+WC_N1+WC_N2+WC_N3+WC_N4)
__global__ void wconv_kernel(const float* __restrict__ s0, const float* __restrict__ s1,
                             const float* __restrict__ s2, const float* __restrict__ s3,
                             const float* __restrict__ s4){
    int i = blockIdx.x * 256 + threadIdx.x;
    if (i >= WC_TOT) return;
    const float* src; __half* dst;
    if (i < WC_N0){ src = s0; dst = g_wcorr_h; }
    else if ((i -= WC_N0) < WC_N1){ src = s1; dst = g_wqkv_h; }
    else if ((i -= WC_N1) < WC_N2){ src = s2; dst = g_wout_h; }
    else if ((i -= WC_N2) < WC_N3){ src = s3; dst = g_wff1_h; }
    else { i -= WC_N3; src = s4; dst = g_wff2_h; }
    float4 v = ((const float4*)src)[i];
    ((uint2*)dst)[i] = make_uint2(pkh2(v.x, v.y), pkh2(v.z, v.w));
}

// ---------------- bilinear (writes f16 feats) ----------------
__global__ void bilinear_kernel(const float* __restrict__ fmaps,
                                const float* __restrict__ coords){
    int bn = blockIdx.x;
    int b  = bn / SEQ;
    int c  = threadIdx.x;
    float xc = coords[(size_t)bn*2 + 0];
    float yc = coords[(size_t)bn*2 + 1];
    xc = fminf(fmaxf(xc, 0.f), (float)(WFm-1));
    yc = fminf(fmaxf(yc, 0.f), (float)(HFm-1));
    float x0 = floorf(xc), y0 = floorf(yc);
    float wx = xc - x0,    wy = yc - y0;
    int x0i = (int)x0, y0i = (int)y0;
    int x1i = min(x0i+1, WFm-1), y1i = min(y0i+1, HFm-1);
    const float* img = fmaps + ((size_t)(b*C2m + c))*HFm*WFm;
    float f00 = img[y0i*WFm + x0i];
    float f01 = img[y0i*WFm + x1i];
    float f10 = img[y1i*WFm + x0i];
    float f11 = img[y1i*WFm + x1i];
    float top = f00*(1.f-wx) + f01*wx;
    float bot = f10*(1.f-wx) + f11*wx;
    g_feats_h[(size_t)bn*C2m + c] = __float2half(top*(1.f-wy) + bot*wy);
}

// ---------------- f16 GEMM with cp.async 4-stage pipeline ----------------
#define BK 32
#define HSTR 20
#define PANEL_U32 (128*HSTR)
#define STAGE_U32 (2*PANEL_U32)
#define GEMM_SMEM (4*STAGE_U32*4)

// variadic: commas inside the epilogue are safe
#define GEMM_BODY(...)                                                          \
    extern __shared__ uint32_t smu[];                                           \
    uint32_t smbase = (uint32_t)__cvta_generic_to_shared(smu);                  \
    int tid = threadIdx.x;                                                      \
    int wid = tid >> 5, lane = tid & 31;                                        \
    int qr = lane >> 2, qc = lane & 3;                                          \
    int warp_m = wid & 3, warp_n = wid >> 2;                                    \
    int m0 = blockIdx.y * 128, n0 = blockIdx.x * 128;                           \
    const __half* Ab = A + (size_t)m0 * K;                                      \
    const __half* Wb = W + (size_t)n0 * K;                                      \
    int crow = tid >> 1;                                                        \
    int ccol = (tid & 1) * 2;                                                   \
    int T = K / BK;                                                             \
    _Pragma("unroll")                                                           \
    for (int s = 0; s < 3; s++){                                                \
        if (s < T){                                                             \
            int k0 = s * BK;                                                    \
            uint32_t base = smbase + (s & 3) * (STAGE_U32*4);                   \
            const __half* as = Ab + (size_t)crow*K + k0 + ccol*8;               \
            const __half* ws = Wb + (size_t)crow*K + k0 + ccol*8;               \
            uint32_t da = base + crow*80 + ccol*16;                             \
            uint32_t db = base + PANEL_U32*4 + crow*80 + ccol*16;               \
            cp16(da, as);      cp16(da + 16, as + 8);                           \
            cp16(db, ws);      cp16(db + 16, ws + 8);                           \
        }                                                                       \
        CP_COMMIT();                                                            \
    }                                                                           \
    float acc[2][8][4];                                                         \
    _Pragma("unroll")                                                           \
    for (int mt = 0; mt < 2; mt++)                                              \
        _Pragma("unroll")                                                       \
        for (int nt = 0; nt < 8; nt++)                                          \
            _Pragma("unroll")                                                   \
            for (int i = 0; i < 4; i++) acc[mt][nt][i] = 0.f;                   \
    for (int t = 0; t < T; t++){                                                \
        CP_WAIT2();                                                             \
        __syncthreads();                                                        \
        if (t + 3 < T){                                                         \
            int k0 = (t+3) * BK;                                                \
            uint32_t base = smbase + ((t+3) & 3) * (STAGE_U32*4);               \
            const __half* as = Ab + (size_t)crow*K + k0 + ccol*8;               \
            const __half* ws = Wb + (size_t)crow*K + k0 + ccol*8;               \
            uint32_t da = base + crow*80 + ccol*16;                             \
            uint32_t db = base + PANEL_U32*4 + crow*80 + ccol*16;               \
            cp16(da, as);      cp16(da + 16, as + 8);                           \
            cp16(db, ws);      cp16(db + 16, ws + 8);                           \
        }                                                                       \
        CP_COMMIT();                                                            \
        const uint32_t* As = smu + (t & 3) * STAGE_U32;                         \
        const uint32_t* Bs = As + PANEL_U32;                                    \
        _Pragma("unroll")                                                       \
        for (int ks = 0; ks < 2; ks++){                                         \
            int k8 = ks * 8;                                                    \
            uint32_t af[2][4];                                                  \
            _Pragma("unroll")                                                   \
            for (int mt = 0; mt < 2; mt++){                                     \
                int r0 = warp_m*32 + mt*16 + qr;                                \
                af[mt][0] = As[ r0     *HSTR + k8 + qc];                        \
                af[mt][1] = As[(r0 + 8)*HSTR + k8 + qc];                        \
                af[mt][2] = As[ r0     *HSTR + k8 + 4 + qc];                    \
                af[mt][3] = As[(r0 + 8)*HSTR + k8 + 4 + qc];                    \
            }                                                                   \
            _Pragma("unroll")                                                   \
            for (int nt = 0; nt < 8; nt++){                                     \
                int cb = warp_n*64 + nt*8 + qr;                                 \
                uint32_t b0 = Bs[cb*HSTR + k8 + qc];                            \
                uint32_t b1 = Bs[cb*HSTR + k8 + 4 + qc];                        \
                mma_f16(acc[0][nt], af[0], b0, b1);                             \
                mma_f16(acc[1][nt], af[1], b0, b1);                             \
            }                                                                   \
        }                                                                       \
    }                                                                           \
    __VA_ARGS__

__global__ __launch_bounds__(256, 2)
void gemm_f16(const __half* __restrict__ A, const __half* __restrict__ W,
              const float* __restrict__ bias, const float* __restrict__ resid,
              float* __restrict__ C, int M, int Nout, int K){
    GEMM_BODY({
        _Pragma("unroll")
        for (int mt = 0; mt < 2; mt++){
            _Pragma("unroll")
            for (int nt = 0; nt < 8; nt++){
                int row = m0 + warp_m*32 + mt*16 + qr;
                int col = n0 + warp_n*64 + nt*8 + qc*2;
                float2 v0 = make_float2(acc[mt][nt][0], acc[mt][nt][1]);
                float2 v1 = make_float2(acc[mt][nt][2], acc[mt][nt][3]);
                if (bias){
                    float2 bb = *(const float2*)(bias + col);
                    v0.x += bb.x; v0.y += bb.y;
                    v1.x += bb.x; v1.y += bb.y;
                }
                size_t off0 = (size_t)row * Nout + col;
                size_t off1 = (size_t)(row + 8) * Nout + col;
                if (resid){
                    float2 r0 = *(const float2*)(resid + off0);
                    float2 r1 = *(const float2*)(resid + off1);
                    v0.x += r0.x; v0.y += r0.y;
                    v1.x += r1.x; v1.y += r1.y;
                }
                *(float2*)(C + off0) = v0;
                *(float2*)(C + off1) = v1;
            }
        }
    })
}

__global__ __launch_bounds__(256, 2)
void gemm_f16_hout(const __half* __restrict__ A, const __half* __restrict__ W,
                   const float* __restrict__ bias,
                   __half* __restrict__ C, int M, int Nout, int K){
    GEMM_BODY({
        _Pragma("unroll")
        for (int mt = 0; mt < 2; mt++){
            _Pragma("unroll")
            for (int nt = 0; nt < 8; nt++){
                int row = m0 + warp_m*32 + mt*16 + qr;
                int col = n0 + warp_n*64 + nt*8 + qc*2;
                float2 v0 = make_float2(acc[mt][nt][0], acc[mt][nt][1]);
                float2 v1 = make_float2(acc[mt][nt][2], acc[mt][nt][3]);
                if (bias){
                    float2 bb = *(const float2*)(bias + col);
                    v0.x += bb.x; v0.y += bb.y;
                    v1.x += bb.x; v1.y += bb.y;
                }
                size_t off0 = (size_t)row * Nout + col;
                size_t off1 = (size_t)(row + 8) * Nout + col;
                *(uint32_t*)(C + off0) = pkh2(v0.x, v0.y);
                *(uint32_t*)(C + off1) = pkh2(v1.x, v1.y);
            }
        }
    })
}

// qkv GEMM with fused per-head RMSNorm + rotary on q,k tiles (v passes through).
// Warp n-tile (64 cols) == one head; rotary pairs (d, d+32) are nt <-> nt+4.
__global__ __launch_bounds__(256, 2)
void gemm_qkv(const __half* __restrict__ A, const __half* __restrict__ W,
              const float* __restrict__ theta,
              const float* __restrict__ sq, const float* __restrict__ sk,
              __half* __restrict__ C, int M, int Nout, int K){
    GEMM_BODY({
        int cbase = n0 + warp_n*64;
        if (cbase < 2*DIM){
            int isK = cbase >= DIM ? 1 : 0;
            int h = (cbase - isK*DIM) >> 6;
            const float* sc = isK ? sk : sq;
            float scl[16];
            _Pragma("unroll")
            for (int nt = 0; nt < 8; nt++){
                float2 s2 = *(const float2*)(sc + nt*8 + qc*2);
                scl[nt*2] = s2.x; scl[nt*2+1] = s2.y;
            }
            _Pragma("unroll")
            for (int mt = 0; mt < 2; mt++){
                _Pragma("unroll")
                for (int rp = 0; rp < 2; rp++){
                    int row = m0 + warp_m*32 + mt*16 + qr + rp*8;
                    float ssq = 0.f;
                    _Pragma("unroll")
                    for (int nt = 0; nt < 8; nt++){
                        float a0 = acc[mt][nt][rp*2];
                        float a1 = acc[mt][nt][rp*2+1];
                        ssq += a0*a0 + a1*a1;
                    }
                    ssq += __shfl_xor_sync(0xFFFFFFFFu, ssq, 1);
                    ssq += __shfl_xor_sync(0xFFFFFFFFu, ssq, 2);
                    float inv = rsqrtf(ssq * (1.f/HDm) + EPSf);
                    int n = row & (SEQ-1);
                    int bb = row >> 11;
                    const float* thp = theta + (((size_t)(bb*NH + h))*SEQ + n)*(HDm/2);
                    _Pragma("unroll")
                    for (int nt = 0; nt < 4; nt++){
                        _Pragma("unroll")
                        for (int j = 0; j < 2; j++){
                            int d = nt*8 + qc*2 + j;
                            float v0 = acc[mt][nt][rp*2+j]   * scl[nt*2+j]     * inv;
                            float v1 = acc[mt][nt+4][rp*2+j] * scl[(nt+4)*2+j] * inv;
                            float th = thp[d];
                            float cs = cosf(th);
                            float sn = sinf(th);
                            acc[mt][nt][rp*2+j]   = v0*cs - v1*sn;
                            acc[mt][nt+4][rp*2+j] = v1*cs + v0*sn;
                        }
                    }
                }
            }
        }
        _Pragma("unroll")
        for (int mt = 0; mt < 2; mt++){
            _Pragma("unroll")
            for (int nt = 0; nt < 8; nt++){
                int row = m0 + warp_m*32 + mt*16 + qr;
                int col = n0 + warp_n*64 + nt*8 + qc*2;
                size_t off0 = (size_t)row * Nout + col;
                size_t off1 = (size_t)(row + 8) * Nout + col;
                *(uint32_t*)(C + off0) = pkh2(acc[mt][nt][0], acc[mt][nt][1]);
                *(uint32_t*)(C + off1) = pkh2(acc[mt][nt][2], acc[mt][nt][3]);
            }
        }
    })
}

// ---------------- RMSNorm over DIM=512 (f32 in, f16 out) ----------------
__global__ void rmsnorm_kernel(const float* __restrict__ X,
                               const float* __restrict__ scale,
                               __half* __restrict__ Y){
    int row = blockIdx.x;
    int t   = threadIdx.x;  // 128
    const float4* x4 = (const float4*)(X + (size_t)row*DIM);
    float4 v = x4[t];
    float ss = v.x*v.x + v.y*v.y + v.z*v.z + v.w*v.w;
    ss = warpSum(ss);
    __shared__ float red[4];
    if ((t & 31) == 0) red[t >> 5] = ss;
    __syncthreads();
    if (t == 0) red[0] = red[0] + red[1] + red[2] + red[3];
    __syncthreads();
    float inv = rsqrtf(red[0] / (float)DIM + EPSf);
    float4 s = ((const float4*)scale)[t];
    ((uint2*)(Y + (size_t)row*DIM))[t] =
        make_uint2(pkh2(v.x*s.x*inv, v.y*s.y*inv), pkh2(v.z*s.z*inv, v.w*s.w*inv));
}

// ---------------- flash attention: K cp.async double-buffer + V reg prefetch ----------------
#define QSTR 36
#define FK0_OFF 0
#define FK1_OFF (128*QSTR)
#define FP_OFF  (2*128*QSTR)
#define FVT_OFF (2*128*QSTR + 128*68)
#define ATTN_SMEM ((2*128*QSTR + 128*68 + 2*64*68)*4)

__global__ __launch_bounds__(256, 2)
void fattn_kernel(const __half* __restrict__ qkv, __half* __restrict__ O){
    extern __shared__ uint32_t smu[];
    uint32_t smbase = (uint32_t)__cvta_generic_to_shared(smu);
    uint32_t* Ps = smu + FP_OFF;

    int tid = threadIdx.x;
    int w = tid >> 5, lane = tid & 31;
    int qr = lane >> 2, qc = lane & 3;
    int bh = blockIdx.x >> 4;
    int qt = blockIdx.x & 15;
    int b = bh >> 3, h = bh & 7;
    int i0 = qt * 128;

    int ldr = tid >> 1;
    int ldc = (tid & 1) * 32;
    int jp = tid >> 2;
    int dg = (tid & 3) * 16;

    const __half* kvbase = qkv + (size_t)b*SEQ*3*DIM;

    {
        const __half* src = kvbase + (size_t)(0 + ldr)*(3*DIM) + DIM + h*HDm + ldc;
        uint32_t da = smbase + (FK0_OFF + ldr*QSTR + (ldc>>1))*4;
        cp16(da, src); cp16(da+16, src+8); cp16(da+32, src+16); cp16(da+48, src+24);
        CP_COMMIT();
    }
    uint32_t av[8], bv[8];
    {
        const __half* vp = kvbase + (size_t)(2*jp)*(3*DIM) + 2*DIM + h*HDm + dg;
        uint4 a0 = *(const uint4*)(vp);
        uint4 a1 = *(const uint4*)(vp + 8);
        uint4 b0v = *(const uint4*)(vp + 3*DIM);
        uint4 b1v = *(const uint4*)(vp + 3*DIM + 8);
        av[0]=a0.x; av[1]=a0.y; av[2]=a0.z; av[3]=a0.w;
        av[4]=a1.x; av[5]=a1.y; av[6]=a1.z; av[7]=a1.w;
        bv[0]=b0v.x; bv[1]=b0v.y; bv[2]=b0v.z; bv[3]=b0v.w;
        bv[4]=b1v.x; bv[5]=b1v.y; bv[6]=b1v.z; bv[7]=b1v.w;
    }
    {
        const __half* src = kvbase + (size_t)(i0 + ldr)*(3*DIM) + h*HDm + ldc;
        uint32_t* dst = smu + FK1_OFF + ldr*QSTR + (ldc>>1);
        *(uint4*)(dst + 0) = *(const uint4*)(src + 0);
        *(uint4*)(dst + 4) = *(const uint4*)(src + 8);
        *(uint4*)(dst + 8) = *(const uint4*)(src + 16);
        *(uint4*)(dst +12) = *(const uint4*)(src + 24);
    }
    __syncthreads();

    uint32_t aQ[4][4];
    {
        const uint32_t* Qs = smu + FK1_OFF;
        #pragma unroll
        for (int ks = 0; ks < 4; ks++){
            int r0 = w*16 + qr;
            aQ[ks][0] = Qs[ r0     *QSTR + ks*8 + qc];
            aQ[ks][1] = Qs[(r0 + 8)*QSTR + ks*8 + qc];
            aQ[ks][2] = Qs[ r0     *QSTR + ks*8 + 4 + qc];
            aQ[ks][3] = Qs[(r0 + 8)*QSTR + ks*8 + 4 + qc];
        }
    }

    float Oacc[8][4];
    #pragma unroll
    for (int nt = 0; nt < 8; nt++)
        #pragma unroll
        for (int i = 0; i < 4; i++) Oacc[nt][i] = 0.f;
    float m0 = -INFINITY, m1 = -INFINITY, l0 = 0.f, l1 = 0.f;

    const int T = SEQ/128;
    for (int t = 0; t < T; t++){
        int buf = t & 1;
        uint32_t* Vt = smu + FVT_OFF + buf*(64*68);
        const uint32_t* Ks = smu + (buf ? FK1_OFF : FK0_OFF);

        #pragma unroll
        for (int i = 0; i < 8; i++){
            int d0 = dg + 2*i;
            int s0 = jp ^ ((((d0  )>>4)&3)<<3);
            int s1 = jp ^ ((((d0+1)>>4)&3)<<3);
            Vt[(d0  )*68 + s0] = __byte_perm(av[i], bv[i], 0x5410);
            Vt[(d0+1)*68 + s1] = __byte_perm(av[i], bv[i], 0x7632);
        }
        CP_WAIT0();
        __syncthreads();

        if (t + 1 < T){
            int j1 = (t+1) * 128;
            uint32_t koff = (buf ? FK0_OFF : FK1_OFF);
            const __half* src = kvbase + (size_t)(j1 + ldr)*(3*DIM) + DIM + h*HDm + ldc;
            uint32_t da = smbase + (koff + ldr*QSTR + (ldc>>1))*4;
            cp16(da, src); cp16(da+16, src+8); cp16(da+32, src+16); cp16(da+48, src+24);
        }
        CP_COMMIT();

        float S[16][4];
        #pragma unroll
        for (int nt = 0; nt < 16; nt++){
            S[nt][0] = S[nt][1] = S[nt][2] = S[nt][3] = 0.f;
            #pragma unroll
            for (int ks = 0; ks < 4; ks++){
                int cb = nt*8 + qr;
                uint32_t b0 = Ks[cb*QSTR + ks*8 + qc];
                uint32_t b1 = Ks[cb*QSTR + ks*8 + 4 + qc];
                mma_f16(S[nt], aQ[ks], b0, b1);
            }
        }

        float mx0 = -INFINITY, mx1 = -INFINITY;
        #pragma unroll
        for (int nt = 0; nt < 16; nt++){
            mx0 = fmaxf(mx0, fmaxf(S[nt][0], S[nt][1]));
            mx1 = fmaxf(mx1, fmaxf(S[nt][2], S[nt][3]));
        }
        mx0 = fmaxf(mx0, __shfl_xor_sync(0xFFFFFFFFu, mx0, 1));
        mx0 = fmaxf(mx0, __shfl_xor_sync(0xFFFFFFFFu, mx0, 2));
        mx1 = fmaxf(mx1, __shfl_xor_sync(0xFFFFFFFFu, mx1, 1));
        mx1 = fmaxf(mx1, __shfl_xor_sync(0xFFFFFFFFu, mx1, 2));
        float nm0 = fmaxf(m0, mx0), nm1 = fmaxf(m1, mx1);
        float sc0 = __expf(m0 - nm0), sc1 = __expf(m1 - nm1);
        m0 = nm0; m1 = nm1;
        float rs0 = 0.f, rs1 = 0.f;
        #pragma unroll
        for (int nt = 0; nt < 16; nt++){
            float p0 = __expf(S[nt][0] - nm0);
            float p1 = __expf(S[nt][1] - nm0);
            float p2 = __expf(S[nt][2] - nm1);
            float p3 = __expf(S[nt][3] - nm1);
            S[nt][0] = p0; S[nt][1] = p1; S[nt][2] = p2; S[nt][3] = p3;
            rs0 += p0 + p1; rs1 += p2 + p3;
        }
        rs0 += __shfl_xor_sync(0xFFFFFFFFu, rs0, 1);
        rs0 += __shfl_xor_sync(0xFFFFFFFFu, rs0, 2);
        rs1 += __shfl_xor_sync(0xFFFFFFFFu, rs1, 1);
        rs1 += __shfl_xor_sync(0xFFFFFFFFu, rs1, 2);
        l0 = l0 * sc0 + rs0;
        l1 = l1 * sc1 + rs1;
        #pragma unroll
        for (int nt = 0; nt < 8; nt++){
            Oacc[nt][0] *= sc0; Oacc[nt][1] *= sc0;
            Oacc[nt][2] *= sc1; Oacc[nt][3] *= sc1;
        }

        {
            int r0 = w*16 + qr, r1 = r0 + 8;
            #pragma unroll
            for (int nt = 0; nt < 16; nt++){
                Ps[r0*68 + nt*4 + qc] = pkh2(S[nt][0], S[nt][1]);
                Ps[r1*68 + nt*4 + qc] = pkh2(S[nt][2], S[nt][3]);
            }
        }

        if (t + 1 < T){
            const __half* vp = kvbase + (size_t)((t+1)*128 + 2*jp)*(3*DIM) + 2*DIM + h*HDm + dg;
            uint4 a0 = *(const uint4*)(vp);
            uint4 a1 = *(const uint4*)(vp + 8);
            uint4 b0v = *(const uint4*)(vp + 3*DIM);
            uint4 b1v = *(const uint4*)(vp + 3*DIM + 8);
            av[0]=a0.x; av[1]=a0.y; av[2]=a0.z; av[3]=a0.w;
            av[4]=a1.x; av[5]=a1.y; av[6]=a1.z; av[7]=a1.w;
            bv[0]=b0v.x; bv[1]=b0v.y; bv[2]=b0v.z; bv[3]=b0v.w;
            bv[4]=b1v.x; bv[5]=b1v.y; bv[6]=b1v.z; bv[7]=b1v.w;
        }
        __syncthreads();

        #pragma unroll
        for (int ks = 0; ks < 8; ks++){
            uint32_t aP[4];
            int r0 = w*16 + qr, r1 = r0 + 8;
            aP[0] = Ps[r0*68 + ks*8 + qc];
            aP[1] = Ps[r1*68 + ks*8 + qc];
            aP[2] = Ps[r0*68 + ks*8 + 4 + qc];
            aP[3] = Ps[r1*68 + ks*8 + 4 + qc];
            #pragma unroll
            for (int nt = 0; nt < 8; nt++){
                int drow = nt*8 + qr;
                int swz = (nt >> 1) << 3;
                uint32_t b0 = Vt[drow*68 + ((ks*8 + qc) ^ swz)];
                uint32_t b1 = Vt[drow*68 + ((ks*8 + 4 + qc) ^ swz)];
                mma_f16(Oacc[nt], aP, b0, b1);
            }
        }
    }

    float il0 = 1.f / l0, il1 = 1.f / l1;
    int row0 = i0 + w*16 + qr, row1 = row0 + 8;
    #pragma unroll
    for (int nt = 0; nt < 8; nt++){
        int col = h*HDm + nt*8 + 2*qc;
        *(uint32_t*)(O + ((size_t)(b*SEQ) + row0)*DIM + col) =
            pkh2(Oacc[nt][0]*il0, Oacc[nt][1]*il0);
        *(uint32_t*)(O + ((size_t)(b*SEQ) + row1)*DIM + col) =
            pkh2(Oacc[nt][2]*il1, Oacc[nt][3]*il1);
    }
}

// ---------------- gated GELU (f16 in, f16 out) ----------------
__global__ void glu_kernel(const __half* __restrict__ Hh, __half* __restrict__ Hg){
    size_t i8 = ((size_t)blockIdx.x * 256 + threadIdx.x) * 8;
    size_t m = i8 / FFm, f = i8 % FFm;
    uint4 hx4 = *(const uint4*)(Hh + m*(2*FFm) + f);
    uint4 g4  = *(const uint4*)(Hh + m*(2*FFm) + FFm + f);
    const uint32_t* hxp = &hx4.x;
    const uint32_t* gp  = &g4.x;
    uint4 o;
    uint32_t* op = &o.x;
    #pragma unroll
    for (int i = 0; i < 4; i++){
        __half2 hh = *reinterpret_cast<const __half2*>(&hxp[i]);
        __half2 gg = *reinterpret_cast<const __half2*>(&gp[i]);
        float2 hf = __half22float2(hh);
        float2 gf = __half22float2(gg);
        op[i] = pkh2(hf.x * geluf(gf.x), hf.y * geluf(gf.y));
    }
    *(uint4*)(Hg + i8) = o;
}

// ---------------- launch ----------------
extern "C" void kernel_launch(void* const* d_in, const int* in_sizes, int n_in,
                              void* d_out, int out_size){
    const float* x       = (const float*)d_in[0];
    const float* theta   = (const float*)d_in[1];
    const float* fmaps   = (const float*)d_in[2];
    const float* coords  = (const float*)d_in[3];
    const float* w_corr  = (const float*)d_in[4];
    const float* norm1   = (const float*)d_in[5];
    const float* sq      = (const float*)d_in[6];
    const float* sk      = (const float*)d_in[7];
    const float* w_qkv   = (const float*)d_in[8];
    const float* w_out   = (const float*)d_in[9];
    const float* norm2   = (const float*)d_in[10];
    const float* w_ff1   = (const float*)d_in[11];
    const float* b_ff1   = (const float*)d_in[12];
    const float* w_ff2   = (const float*)d_in[13];
    float* out = (float*)d_out;

    float *p_x, *p_x2;
    __half *p_feats, *p_xn, *p_qkvh, *p_o, *p_xn2, *p_hh, *p_hg;
    __half *p_wc, *p_wq, *p_wo, *p_w1, *p_w2;
    cudaGetSymbolAddress((void**)&p_x,     g_x);
    cudaGetSymbolAddress((void**)&p_x2,    g_x2);
    cudaGetSymbolAddress((void**)&p_feats, g_feats_h);
    cudaGetSymbolAddress((void**)&p_xn,    g_xn_h);
    cudaGetSymbolAddress((void**)&p_qkvh,  g_qkv_h);
    cudaGetSymbolAddress((void**)&p_o,     g_o_h);
    cudaGetSymbolAddress((void**)&p_xn2,   g_xn2_h);
    cudaGetSymbolAddress((void**)&p_hh,    g_hh);
    cudaGetSymbolAddress((void**)&p_hg,    g_hg_h);
    cudaGetSymbolAddress((void**)&p_wc,    g_wcorr_h);
    cudaGetSymbolAddress((void**)&p_wq,    g_wqkv_h);
    cudaGetSymbolAddress((void**)&p_wo,    g_wout_h);
    cudaGetSymbolAddress((void**)&p_w1,    g_wff1_h);
    cudaGetSymbolAddress((void**)&p_w2,    g_wff2_h);

    static bool cfg = false;
    if (!cfg){
        cudaFuncSetAttribute(fattn_kernel, cudaFuncAttributeMaxDynamicSharedMemorySize,
                             ATTN_SMEM);
        cudaFuncSetAttribute(gemm_f16, cudaFuncAttributeMaxDynamicSharedMemorySize,
                             GEMM_SMEM);
        cudaFuncSetAttribute(gemm_f16_hout, cudaFuncAttributeMaxDynamicSharedMemorySize,
                             GEMM_SMEM);
        cudaFuncSetAttribute(gemm_qkv, cudaFuncAttributeMaxDynamicSharedMemorySize,
                             GEMM_SMEM);
        cfg = true;
    }

    const int M = Bsz * SEQ;   // 8192

    wconv_kernel<<<(WC_TOT + 255)/256, 256>>>(w_corr, w_qkv, w_out, w_ff1, w_ff2);
    bilinear_kernel<<<M, C2m>>>(fmaps, coords);
    gemm_f16<<<dim3(DIM/128, M/128), 256, GEMM_SMEM>>>(p_feats, p_wc, nullptr, x, p_x, M, DIM, C2m);
    rmsnorm_kernel<<<M, 128>>>(p_x, norm1, p_xn);
    gemm_qkv<<<dim3(3*DIM/128, M/128), 256, GEMM_SMEM>>>(p_xn, p_wq, theta, sq, sk, p_qkvh, M, 3*DIM, DIM);
    fattn_kernel<<<Bsz*NH*(SEQ/128), 256, ATTN_SMEM>>>(p_qkvh, p_o);
    gemm_f16<<<dim3(DIM/128, M/128), 256, GEMM_SMEM>>>(p_o, p_wo, nullptr, p_x, p_x2, M, DIM, DIM);
    rmsnorm_kernel<<<M, 128>>>(p_x2, norm2, p_xn2);
    gemm_f16_hout<<<dim3(2*FFm/128, M/128), 256, GEMM_SMEM>>>(p_xn2, p_w1, b_ff1, p_hh, M, 2*FFm, DIM);
    glu_kernel<<<(Bsz*SEQ*FFm)/2048, 256>>>(p_hh, p_hg);
    gemm_f16<<<dim3(DIM/128, M/128), 256, GEMM_SMEM>>>(p_hg, p_w2, nullptr, p_x2, out, M, DIM, FFm);
}